// round 1
// baseline (speedup 1.0000x reference)
#include <cuda_runtime.h>

// Problem constants (hard-coded per reference: H=51, L=3, IN=2, B=1024, T=2048)
#define Hh   51
#define Gg   204      // 4*H
#define BT   8        // batch elems per CTA
#define Tt   2048
#define Bb   1024
#define CH   32       // input staging chunk (timesteps)
#define NTH  256
#define NCTA 128      // Bb / BT

// Shared memory layout (floats)
//  w_hh0  10404 | w_ih1 10404 | w_hh1 10404 | w_ih2 10404 | w_hh2 10404
//  w_ih0  408   | bias 612 (b_ih+b_hh per layer) | wlin 102 | blin 2
//  hbuf   3*408 | cbuf 3*408 | gates 204*8 | xs CH*8*2
#define SM_FLOATS (10404*5 + 408 + 612 + 102 + 2 + 1224 + 1224 + 1632 + 512)
#define SM_BYTES  (SM_FLOATS * 4)   // 230944 B  (< 232448 limit)

__device__ __forceinline__ float sigm_f(float x) {
    // 1/(1+e^-x): MUFU.EX2 + MUFU.RCP path, rel err ~1e-6
    return __fdividef(1.0f, 1.0f + __expf(-x));
}
__device__ __forceinline__ float tanh_f(float x) {
    // 1 - 2/(e^{2x}+1): saturates correctly at +-1 for |x| large
    return 1.0f - __fdividef(2.0f, __expf(2.0f * x) + 1.0f);
}

// Gate matvec for cells 1,2: gates[r][b] = bias[r] + Wih[r,:]*x[:,b] + Whh[r,:]*h[:,b]
__device__ __forceinline__ void matvec_hh(
    int r,
    const float* __restrict__ wx, const float* __restrict__ wh,
    const float* __restrict__ x,  const float* __restrict__ h,
    float b0, float* __restrict__ gates)
{
    float acc[BT];
#pragma unroll
    for (int b = 0; b < BT; b++) acc[b] = b0;
    const float* wxr = wx + r * Hh;
    const float* whr = wh + r * Hh;
#pragma unroll
    for (int k = 0; k < Hh; k++) {
        float wi = wxr[k];
        float wv = whr[k];
        float4 xa = *(const float4*)(x + k * 8);
        float4 xb = *(const float4*)(x + k * 8 + 4);
        float4 ha = *(const float4*)(h + k * 8);
        float4 hb = *(const float4*)(h + k * 8 + 4);
        acc[0] = fmaf(wi, xa.x, acc[0]); acc[0] = fmaf(wv, ha.x, acc[0]);
        acc[1] = fmaf(wi, xa.y, acc[1]); acc[1] = fmaf(wv, ha.y, acc[1]);
        acc[2] = fmaf(wi, xa.z, acc[2]); acc[2] = fmaf(wv, ha.z, acc[2]);
        acc[3] = fmaf(wi, xa.w, acc[3]); acc[3] = fmaf(wv, ha.w, acc[3]);
        acc[4] = fmaf(wi, xb.x, acc[4]); acc[4] = fmaf(wv, hb.x, acc[4]);
        acc[5] = fmaf(wi, xb.y, acc[5]); acc[5] = fmaf(wv, hb.y, acc[5]);
        acc[6] = fmaf(wi, xb.z, acc[6]); acc[6] = fmaf(wv, hb.z, acc[6]);
        acc[7] = fmaf(wi, xb.w, acc[7]); acc[7] = fmaf(wv, hb.w, acc[7]);
    }
    *(float4*)(gates + r * 8)     = make_float4(acc[0], acc[1], acc[2], acc[3]);
    *(float4*)(gates + r * 8 + 4) = make_float4(acc[4], acc[5], acc[6], acc[7]);
}

__global__ void __launch_bounds__(NTH, 1) lstm_persistent_kernel(
    const float* __restrict__ g_input, const float* __restrict__ g_time,
    const float* __restrict__ Wih0, const float* __restrict__ Whh0,
    const float* __restrict__ bih0, const float* __restrict__ bhh0,
    const float* __restrict__ Wih1, const float* __restrict__ Whh1,
    const float* __restrict__ bih1, const float* __restrict__ bhh1,
    const float* __restrict__ Wih2, const float* __restrict__ Whh2,
    const float* __restrict__ bih2, const float* __restrict__ bhh2,
    const float* __restrict__ Wlin, const float* __restrict__ blin_g,
    float* __restrict__ out)
{
    extern __shared__ float sm[];
    float* w_hh0 = sm;
    float* w_ih1 = w_hh0 + 10404;
    float* w_hh1 = w_ih1 + 10404;
    float* w_ih2 = w_hh1 + 10404;
    float* w_hh2 = w_ih2 + 10404;
    float* w_ih0 = w_hh2 + 10404;   // 408
    float* bias  = w_ih0 + 408;     // 612 (3 layers x 204, b_ih+b_hh combined)
    float* wlin  = bias  + 612;     // 102
    float* blin  = wlin  + 102;     // 2
    float* hbuf  = blin  + 2;       // 3 * 408, layout [layer][k][b]
    float* cbuf  = hbuf  + 1224;    // 3 * 408
    float* gates = cbuf  + 1224;    // 204 * 8, layout [row][b]
    float* xs    = gates + 1632;    // CH * 8 * 2

    const int tid = threadIdx.x;
    const int b0g = blockIdx.x * BT;

    // ---- load weights into SMEM ----
    for (int i = tid; i < 10404; i += NTH) {
        w_hh0[i] = Whh0[i];
        w_ih1[i] = Wih1[i];
        w_hh1[i] = Whh1[i];
        w_ih2[i] = Wih2[i];
        w_hh2[i] = Whh2[i];
    }
    for (int i = tid; i < 408; i += NTH) w_ih0[i] = Wih0[i];
    if (tid < 204) {
        bias[tid]       = bih0[tid] + bhh0[tid];
        bias[204 + tid] = bih1[tid] + bhh1[tid];
        bias[408 + tid] = bih2[tid] + bhh2[tid];
    }
    if (tid < 102) wlin[tid] = Wlin[tid];
    if (tid < 2)   blin[tid] = blin_g[tid];
    for (int i = tid; i < 1224; i += NTH) { hbuf[i] = 0.0f; cbuf[i] = 0.0f; }
    __syncthreads();

    const int r = tid;               // gate row for matvec phases (active if < 204)
    const bool mv = (tid < Gg);

    for (int t = 0; t < Tt; t++) {
        // ---- stage a chunk of inputs every CH steps ----
        if ((t & (CH - 1)) == 0) {
            int b = tid >> 5;        // 0..7
            int i = tid & 31;        // 0..31
            size_t gidx = (size_t)(b0g + b) * Tt + t + i;
            xs[(i * 8 + b) * 2 + 0] = g_input[gidx];
            xs[(i * 8 + b) * 2 + 1] = g_time[gidx];
            __syncthreads();
        }
        const int ti = t & (CH - 1);

        // ================= cell 0 =================
        if (mv) {
            float xv0[BT], xv1[BT];
#pragma unroll
            for (int b = 0; b < BT; b++) {
                xv0[b] = xs[(ti * 8 + b) * 2 + 0];
                xv1[b] = xs[(ti * 8 + b) * 2 + 1];
            }
            float wi0 = w_ih0[r * 2 + 0];
            float wi1 = w_ih0[r * 2 + 1];
            float acc[BT];
#pragma unroll
            for (int b = 0; b < BT; b++) {
                acc[b] = bias[r];
                acc[b] = fmaf(wi0, xv0[b], acc[b]);
                acc[b] = fmaf(wi1, xv1[b], acc[b]);
            }
            const float* whr = w_hh0 + r * Hh;
            const float* h0  = hbuf;
#pragma unroll
            for (int k = 0; k < Hh; k++) {
                float wv = whr[k];
                float4 ha = *(const float4*)(h0 + k * 8);
                float4 hb = *(const float4*)(h0 + k * 8 + 4);
                acc[0] = fmaf(wv, ha.x, acc[0]);
                acc[1] = fmaf(wv, ha.y, acc[1]);
                acc[2] = fmaf(wv, ha.z, acc[2]);
                acc[3] = fmaf(wv, ha.w, acc[3]);
                acc[4] = fmaf(wv, hb.x, acc[4]);
                acc[5] = fmaf(wv, hb.y, acc[5]);
                acc[6] = fmaf(wv, hb.z, acc[6]);
                acc[7] = fmaf(wv, hb.w, acc[7]);
            }
            *(float4*)(gates + r * 8)     = make_float4(acc[0], acc[1], acc[2], acc[3]);
            *(float4*)(gates + r * 8 + 4) = make_float4(acc[4], acc[5], acc[6], acc[7]);
        }
        __syncthreads();

        // ---- update layer 0 ----
        {
            float* hp = hbuf;
            float* cp = cbuf;
#pragma unroll 2
            for (int idx = tid; idx < Hh * BT; idx += NTH) {
                int jj = idx >> 3, b = idx & 7;
                float gi = gates[( 0 + jj) * 8 + b];
                float gf = gates[(51 + jj) * 8 + b];
                float gg = gates[(102 + jj) * 8 + b];
                float go = gates[(153 + jj) * 8 + b];
                float cn = sigm_f(gf) * cp[jj * 8 + b] + sigm_f(gi) * tanh_f(gg);
                cp[jj * 8 + b] = cn;
                hp[jj * 8 + b] = sigm_f(go) * tanh_f(cn);
            }
        }
        __syncthreads();

        // ================= cell 1 =================
        if (mv) matvec_hh(r, w_ih1, w_hh1, hbuf, hbuf + 408, bias[204 + r], gates);
        __syncthreads();
        {
            float* hp = hbuf + 408;
            float* cp = cbuf + 408;
#pragma unroll 2
            for (int idx = tid; idx < Hh * BT; idx += NTH) {
                int jj = idx >> 3, b = idx & 7;
                float gi = gates[( 0 + jj) * 8 + b];
                float gf = gates[(51 + jj) * 8 + b];
                float gg = gates[(102 + jj) * 8 + b];
                float go = gates[(153 + jj) * 8 + b];
                float cn = sigm_f(gf) * cp[jj * 8 + b] + sigm_f(gi) * tanh_f(gg);
                cp[jj * 8 + b] = cn;
                hp[jj * 8 + b] = sigm_f(go) * tanh_f(cn);
            }
        }
        __syncthreads();

        // ================= cell 2 =================
        if (mv) matvec_hh(r, w_ih2, w_hh2, hbuf + 408, hbuf + 816, bias[408 + r], gates);
        __syncthreads();
        {
            float* hp = hbuf + 816;
            float* cp = cbuf + 816;
#pragma unroll 2
            for (int idx = tid; idx < Hh * BT; idx += NTH) {
                int jj = idx >> 3, b = idx & 7;
                float gi = gates[( 0 + jj) * 8 + b];
                float gf = gates[(51 + jj) * 8 + b];
                float gg = gates[(102 + jj) * 8 + b];
                float go = gates[(153 + jj) * 8 + b];
                float cn = sigm_f(gf) * cp[jj * 8 + b] + sigm_f(gi) * tanh_f(gg);
                cp[jj * 8 + b] = cn;
                hp[jj * 8 + b] = sigm_f(go) * tanh_f(cn);
            }
        }
        __syncthreads();

        // ---- linear head + softplus (runs concurrently with next iter's staging) ----
        if (tid < 16) {
            int b = tid >> 1, o = tid & 1;
            const float* h2 = hbuf + 816;
            const float* wl = wlin + o * Hh;
            float z = blin[o];
#pragma unroll
            for (int k = 0; k < Hh; k++) z = fmaf(wl[k], h2[k * 8 + b], z);
            if (o == 1) z = (z > 30.0f) ? z : log1pf(__expf(z));
            out[((size_t)(b0g + b)) * Tt * 2 + (size_t)t * 2 + o] = z;
        }
        // no extra sync needed: next phases don't touch h2/out before the next barrier
    }
}

extern "C" void kernel_launch(void* const* d_in, const int* in_sizes, int n_in,
                              void* d_out, int out_size)
{
    const float* input = (const float*)d_in[0];
    const float* timei = (const float*)d_in[1];
    const float* Wih0  = (const float*)d_in[2];
    const float* Whh0  = (const float*)d_in[3];
    const float* bih0  = (const float*)d_in[4];
    const float* bhh0  = (const float*)d_in[5];
    const float* Wih1  = (const float*)d_in[6];
    const float* Whh1  = (const float*)d_in[7];
    const float* bih1  = (const float*)d_in[8];
    const float* bhh1  = (const float*)d_in[9];
    const float* Wih2  = (const float*)d_in[10];
    const float* Whh2  = (const float*)d_in[11];
    const float* bih2  = (const float*)d_in[12];
    const float* bhh2  = (const float*)d_in[13];
    const float* Wlin  = (const float*)d_in[14];
    const float* blin  = (const float*)d_in[15];
    float* out = (float*)d_out;

    cudaFuncSetAttribute(lstm_persistent_kernel,
                         cudaFuncAttributeMaxDynamicSharedMemorySize, SM_BYTES);

    lstm_persistent_kernel<<<NCTA, NTH, SM_BYTES>>>(
        input, timei,
        Wih0, Whh0, bih0, bhh0,
        Wih1, Whh1, bih1, bhh1,
        Wih2, Whh2, bih2, bhh2,
        Wlin, blin, out);
}